// round 13
// baseline (speedup 1.0000x reference)
#include <cuda_runtime.h>
#include <cuda_bf16.h>
#include <mma.h>
#include <math.h>
#include <stdint.h>

using namespace nvcuda;

// Problem constants (fixed shapes)
#define B_DIM 8192
#define D_DIM 512
#define H_DIM 4
#define M_DIM 128
#define W_DIM 64
#define N_DIM (H_DIM * W_DIM)   // 256
#define EPS 1e-6f

// Scratch for tanh(hidden @ W_key + b_key): [B, 256] fp32 = 8 MB
__device__ float g_key[(size_t)B_DIM * N_DIM];

// ---------------------------------------------------------------------------
// Kernel A: bf16 split-GEMM on tensor cores, with FUSED fp32->bf16 hi/lo
// conversion in the tile stage (no separate split kernel, no bf16 scratch).
// key = tanh( Ah@Wh + Ah@Wl + Al@Wh + b )
// Block tile 64x128, 8 warps (2 row-groups x 4 col-groups), warp tile 32x32.
// K-chunk 32. Grid = (2, 128) = 256 blocks -> 2 CTAs/SM.
// ---------------------------------------------------------------------------
#define GBM 64
#define GBN 128
#define KB 32
#define APITCH 40     // bf16 elems per A smem row
#define BPITCH 136    // bf16 elems per B smem row

// smem bytes: Ah 64*40*2=5120, Al 5120, Bh 32*136*2=8704, Bl 8704 -> 27648
#define SM_AH 0
#define SM_AL 5120
#define SM_BH 10240
#define SM_BL 18944
#define SM_TOTAL 27648
#define EPI_PITCH 24

__device__ __forceinline__ void cvt_split4(float4 v, uint2* hi, uint2* lo)
{
    float x[4] = {v.x, v.y, v.z, v.w};
    __align__(8) __nv_bfloat16 h[4], l[4];
    #pragma unroll
    for (int j = 0; j < 4; j++) {
        h[j] = __float2bfloat16(x[j]);
        l[j] = __float2bfloat16(x[j] - __bfloat162float(h[j]));
    }
    *hi = *(uint2*)h;
    *lo = *(uint2*)l;
}

__global__ __launch_bounds__(256)
void key_gemm_kernel(const float* __restrict__ A,      // hidden [B, 512]
                     const float* __restrict__ Wk,     // [512, 256]
                     const float* __restrict__ bk,     // [256]
                     float* __restrict__ out)          // g_key [B, 256]
{
    __shared__ __align__(16) unsigned char smem_raw[SM_TOTAL];
    __nv_bfloat16* Ah = (__nv_bfloat16*)(smem_raw + SM_AH);
    __nv_bfloat16* Al = (__nv_bfloat16*)(smem_raw + SM_AL);
    __nv_bfloat16* Bh = (__nv_bfloat16*)(smem_raw + SM_BH);
    __nv_bfloat16* Bl = (__nv_bfloat16*)(smem_raw + SM_BL);

    const int tid  = threadIdx.x;
    const int warp = tid >> 5;
    const int lane = tid & 31;
    const int wr   = warp >> 2;          // 0..1 (32 rows each)
    const int wc   = warp & 3;           // 0..3 (32 cols each)

    const int row0 = blockIdx.y * GBM;
    const int col0 = blockIdx.x * GBN;

    // A tile: 64x32 fp32 = 512 float4 -> 2 per thread (row = f>>3, c4 = f&7)
    const int aR0 = tid >> 3,          aC0 = (tid & 7) * 4;
    const int aR1 = (tid + 256) >> 3,  aC1 = (tid & 7) * 4;   // f&7 same
    // W tile: 32x128 fp32 = 1024 float4 -> 4 per thread (row = f>>5, c4 = f&31)
    int wR[4], wC[4];
    #pragma unroll
    for (int i = 0; i < 4; i++) {
        int f = tid + i * 256;
        wR[i] = f >> 5;
        wC[i] = (f & 31) * 4;
    }

    wmma::fragment<wmma::accumulator, 16, 16, 16, float> acc[2][2];
    #pragma unroll
    for (int i = 0; i < 2; i++)
        #pragma unroll
        for (int j = 0; j < 2; j++)
            wmma::fill_fragment(acc[i][j], 0.0f);

    const int NSTEP = D_DIM / KB;   // 16

    // prologue: fetch chunk 0 into registers
    float4 pa0 = *(const float4*)&A[(size_t)(row0 + aR0) * D_DIM + aC0];
    float4 pa1 = *(const float4*)&A[(size_t)(row0 + aR1) * D_DIM + aC1];
    float4 pw[4];
    #pragma unroll
    for (int i = 0; i < 4; i++)
        pw[i] = *(const float4*)&Wk[(size_t)wR[i] * N_DIM + col0 + wC[i]];

    #pragma unroll 1
    for (int s = 0; s < NSTEP; s++) {
        // convert + store current chunk to smem
        {
            uint2 h, l;
            cvt_split4(pa0, &h, &l);
            *(uint2*)&Ah[aR0 * APITCH + aC0] = h;
            *(uint2*)&Al[aR0 * APITCH + aC0] = l;
            cvt_split4(pa1, &h, &l);
            *(uint2*)&Ah[aR1 * APITCH + aC1] = h;
            *(uint2*)&Al[aR1 * APITCH + aC1] = l;
            #pragma unroll
            for (int i = 0; i < 4; i++) {
                cvt_split4(pw[i], &h, &l);
                *(uint2*)&Bh[wR[i] * BPITCH + wC[i]] = h;
                *(uint2*)&Bl[wR[i] * BPITCH + wC[i]] = l;
            }
        }
        __syncthreads();

        // prefetch next chunk (overlaps the MMA section)
        if (s + 1 < NSTEP) {
            int k0n = (s + 1) * KB;
            pa0 = *(const float4*)&A[(size_t)(row0 + aR0) * D_DIM + k0n + aC0];
            pa1 = *(const float4*)&A[(size_t)(row0 + aR1) * D_DIM + k0n + aC1];
            #pragma unroll
            for (int i = 0; i < 4; i++)
                pw[i] = *(const float4*)&Wk[(size_t)(k0n + wR[i]) * N_DIM + col0 + wC[i]];
        }

        #pragma unroll
        for (int kk = 0; kk < KB; kk += 16) {
            wmma::fragment<wmma::matrix_a, 16, 16, 16, __nv_bfloat16, wmma::row_major> fah[2], fal[2];
            wmma::fragment<wmma::matrix_b, 16, 16, 16, __nv_bfloat16, wmma::row_major> fbh[2], fbl[2];
            #pragma unroll
            for (int i = 0; i < 2; i++) {
                wmma::load_matrix_sync(fah[i], &Ah[(wr * 32 + i * 16) * APITCH + kk], APITCH);
                wmma::load_matrix_sync(fal[i], &Al[(wr * 32 + i * 16) * APITCH + kk], APITCH);
            }
            #pragma unroll
            for (int j = 0; j < 2; j++) {
                wmma::load_matrix_sync(fbh[j], &Bh[kk * BPITCH + wc * 32 + j * 16], BPITCH);
                wmma::load_matrix_sync(fbl[j], &Bl[kk * BPITCH + wc * 32 + j * 16], BPITCH);
            }
            #pragma unroll
            for (int i = 0; i < 2; i++)
                #pragma unroll
                for (int j = 0; j < 2; j++) {
                    wmma::mma_sync(acc[i][j], fah[i], fbh[j], acc[i][j]);
                    wmma::mma_sync(acc[i][j], fah[i], fbl[j], acc[i][j]);
                    wmma::mma_sync(acc[i][j], fal[i], fbh[j], acc[i][j]);
                }
        }
        __syncthreads();
    }

    // ---- epilogue: per-warp smem staging -> tanh(+bias) -> coalesced store
    // Each 16x16 tile: 2 lanes per row, each lane covers 8 columns (TWO
    // float4s at ec and ec+4) -> all 16 columns written.
    float* scr = (float*)(smem_raw) + warp * 16 * EPI_PITCH;   // 1536 B/warp
    const int er = lane >> 1;            // 0..15 row within tile
    const int ec = (lane & 1) * 8;       // col half (8 floats)

    #pragma unroll
    for (int i = 0; i < 2; i++) {
        #pragma unroll
        for (int j = 0; j < 2; j++) {
            wmma::store_matrix_sync(scr, acc[i][j], EPI_PITCH, wmma::mem_row_major);
            __syncwarp();
            const int gr = row0 + wr * 32 + i * 16 + er;
            const int gc = col0 + wc * 32 + j * 16 + ec;
            float4 c0 = *(float4*)&scr[er * EPI_PITCH + ec];
            float4 c1 = *(float4*)&scr[er * EPI_PITCH + ec + 4];
            float4 b0 = __ldg((const float4*)&bk[gc]);
            float4 b1 = __ldg((const float4*)&bk[gc + 4]);
            float4 o0, o1;
            o0.x = tanhf(c0.x + b0.x); o0.y = tanhf(c0.y + b0.y);
            o0.z = tanhf(c0.z + b0.z); o0.w = tanhf(c0.w + b0.w);
            o1.x = tanhf(c1.x + b1.x); o1.y = tanhf(c1.y + b1.y);
            o1.z = tanhf(c1.z + b1.z); o1.w = tanhf(c1.w + b1.w);
            *(float4*)&out[(size_t)gr * N_DIM + gc]     = o0;
            *(float4*)&out[(size_t)gr * N_DIM + gc + 4] = o1;
            __syncwarp();
        }
    }
}

// ---------------------------------------------------------------------------
// Kernel B: one-shot attention (round-9 proven). 256 threads per batch row.
// Tile via ONE cp.async.bulk into linear smem + mbarrier; read-side XOR
// permutation keeps LDS.128 conflict-free.
// ---------------------------------------------------------------------------
#define ATT_THREADS 256
#define ATT_SMEM (M_DIM * W_DIM * 4)   // 32768 bytes, linear [128][16] float4

__global__ __launch_bounds__(ATT_THREADS, 6)
void attn_kernel(const float* __restrict__ hidden,   // [B, 512]
                 const float* __restrict__ memory,   // [B, 128, 64]
                 const float* __restrict__ Wb,       // [512, 4]
                 const float* __restrict__ bb,       // [4]
                 const float* __restrict__ key,      // g_key [B, 256]
                 float* __restrict__ out)            // [B, 4, 128]
{
    extern __shared__ float4 tile[];                 // [128][16] linear

    __shared__ float4 key4[N_DIM / 4];
    __shared__ float  u2_s[H_DIM];
    __shared__ float  beta_s[H_DIM];
    __shared__ float4 bpart[4];
    __shared__ float4 red_s[8];
    __shared__ __align__(8) unsigned long long mbar;

    const int b    = blockIdx.x;
    const int tid  = threadIdx.x;
    const int lane = tid & 31;
    const int warp = tid >> 5;
    const int m    = tid >> 1;
    const int half = tid & 1;

    const unsigned int mbar_a =
        (unsigned int)__cvta_generic_to_shared(&mbar);

    if (tid == 0) {
        asm volatile("mbarrier.init.shared.b64 [%0], 1;" :: "r"(mbar_a) : "memory");
        asm volatile("fence.proxy.async.shared::cta;" ::: "memory");
    }
    __syncthreads();
    if (tid == 0) {
        const void* gp = (const void*)&memory[(size_t)b * M_DIM * W_DIM];
        unsigned int dst = (unsigned int)__cvta_generic_to_shared(tile);
        asm volatile("mbarrier.arrive.expect_tx.shared.b64 _, [%0], %1;"
                     :: "r"(mbar_a), "r"(ATT_SMEM) : "memory");
        asm volatile("cp.async.bulk.shared::cta.global.mbarrier::complete_tx::bytes "
                     "[%0], [%1], %2, [%3];"
                     :: "r"(dst), "l"(gp), "r"(ATT_SMEM), "r"(mbar_a) : "memory");
    }

    const float4* keyrow4 = (const float4*)&key[(size_t)b * N_DIM];

    if (warp < 4) {
        const float4* h4 = (const float4*)&hidden[(size_t)b * D_DIM];
        float4 hv = h4[warp * 32 + lane];
        const float4* wb4 = (const float4*)Wb;
        int d0 = warp * 128 + lane * 4;
        float4 w0 = wb4[d0 + 0], w1 = wb4[d0 + 1], w2 = wb4[d0 + 2], w3 = wb4[d0 + 3];
        float4 p;
        p.x = hv.x * w0.x + hv.y * w1.x + hv.z * w2.x + hv.w * w3.x;
        p.y = hv.x * w0.y + hv.y * w1.y + hv.z * w2.y + hv.w * w3.y;
        p.z = hv.x * w0.z + hv.y * w1.z + hv.z * w2.z + hv.w * w3.z;
        p.w = hv.x * w0.w + hv.y * w1.w + hv.z * w2.w + hv.w * w3.w;
        #pragma unroll
        for (int off = 16; off > 0; off >>= 1) {
            p.x += __shfl_xor_sync(0xffffffffu, p.x, off);
            p.y += __shfl_xor_sync(0xffffffffu, p.y, off);
            p.z += __shfl_xor_sync(0xffffffffu, p.z, off);
            p.w += __shfl_xor_sync(0xffffffffu, p.w, off);
        }
        if (lane == 0) bpart[warp] = p;
    } else if (warp < 6) {
        int idx = (warp - 4) * 32 + lane;
        key4[idx] = keyrow4[idx];
    } else {
        int idx = (warp - 6) * 32 + lane;
        float4 v = keyrow4[idx];
        float ss = v.x * v.x + v.y * v.y + v.z * v.z + v.w * v.w;
        #pragma unroll
        for (int off = 8; off > 0; off >>= 1)
            ss += __shfl_xor_sync(0xffffffffu, ss, off);
        if ((lane & 15) == 0)
            u2_s[(warp - 6) * 2 + (lane >> 4)] = ss + EPS;
    }

    {
        asm volatile(
            "{\n\t"
            ".reg .pred P;\n"
            "WAIT_%=:\n\t"
            "mbarrier.try_wait.parity.acquire.cta.shared::cta.b64 P, [%0], 0;\n\t"
            "@P bra DONE_%=;\n\t"
            "bra WAIT_%=;\n"
            "DONE_%=:\n\t"
            "}"
            :: "r"(mbar_a) : "memory");
    }
    __syncthreads();

    if (tid < H_DIM) {
        float s = ((const float*)&bpart[0])[tid] + ((const float*)&bpart[1])[tid]
                + ((const float*)&bpart[2])[tid] + ((const float*)&bpart[3])[tid]
                + bb[tid];
        beta_s[tid] = (s > 15.f) ? s : __logf(1.f + __expf(s));
    }

    const int perm = ((m & 3) << 1) | half;
    float v2 = 0.f;
    float num[H_DIM] = {0.f, 0.f, 0.f, 0.f};
    #pragma unroll
    for (int i = 0; i < 8; i++) {
        int ws = (half * 8 + i) ^ perm;
        float4 v = tile[m * 16 + ws];
        v2 += v.x * v.x + v.y * v.y + v.z * v.z + v.w * v.w;
        #pragma unroll
        for (int h = 0; h < H_DIM; h++) {
            float4 kh = key4[h * 16 + ws];
            num[h] += kh.x * v.x + kh.y * v.y + kh.z * v.z + kh.w * v.w;
        }
    }
    #pragma unroll
    for (int h = 0; h < H_DIM; h++)
        num[h] += __shfl_xor_sync(0xffffffffu, num[h], 1);
    v2 += __shfl_xor_sync(0xffffffffu, v2, 1);
    v2 += EPS;

    __syncthreads();

    float e[H_DIM];
    #pragma unroll
    for (int h = 0; h < H_DIM; h++) {
        float den = sqrtf(u2_s[h] * v2);
        float kk  = num[h] / (den + EPS);
        e[h] = __expf(kk * beta_s[h]);
    }

    {
        float4 es = make_float4(e[0], e[1], e[2], e[3]);
        #pragma unroll
        for (int off = 16; off > 0; off >>= 1) {
            es.x += __shfl_xor_sync(0xffffffffu, es.x, off);
            es.y += __shfl_xor_sync(0xffffffffu, es.y, off);
            es.z += __shfl_xor_sync(0xffffffffu, es.z, off);
            es.w += __shfl_xor_sync(0xffffffffu, es.w, off);
        }
        if (lane == 0) red_s[warp] = es;
    }
    __syncthreads();

    float4 t0 = red_s[0], t1 = red_s[1], t2 = red_s[2], t3 = red_s[3];
    float4 t4 = red_s[4], t5 = red_s[5], t6 = red_s[6], t7 = red_s[7];
    float sm[H_DIM];
    sm[0] = 0.5f * (t0.x + t1.x + t2.x + t3.x + t4.x + t5.x + t6.x + t7.x);
    sm[1] = 0.5f * (t0.y + t1.y + t2.y + t3.y + t4.y + t5.y + t6.y + t7.y);
    sm[2] = 0.5f * (t0.z + t1.z + t2.z + t3.z + t4.z + t5.z + t6.z + t7.z);
    sm[3] = 0.5f * (t0.w + t1.w + t2.w + t3.w + t4.w + t5.w + t6.w + t7.w);

    #pragma unroll
    for (int j = 0; j < 2; j++) {
        int h = half * 2 + j;
        out[((size_t)b * H_DIM + h) * M_DIM + m] = e[h] / sm[h];
    }
}

// ---------------------------------------------------------------------------
// Launch
// ---------------------------------------------------------------------------
extern "C" void kernel_launch(void* const* d_in, const int* in_sizes, int n_in,
                              void* d_out, int out_size)
{
    const float* hidden = (const float*)d_in[0];   // [8192, 512]
    const float* memory = (const float*)d_in[1];   // [8192, 128, 64]
    const float* W_key  = (const float*)d_in[2];   // [512, 256]
    const float* b_key  = (const float*)d_in[3];   // [256]
    const float* W_beta = (const float*)d_in[4];   // [512, 4]
    const float* b_beta = (const float*)d_in[5];   // [4]
    float* out = (float*)d_out;                    // [8192, 4, 128]

    float* keybuf;
    cudaGetSymbolAddress((void**)&keybuf, g_key);

    dim3 gridA(N_DIM / GBN, B_DIM / GBM);   // (2, 128) = 256 blocks
    key_gemm_kernel<<<gridA, 256>>>(hidden, W_key, b_key, keybuf);

    attn_kernel<<<B_DIM, ATT_THREADS, ATT_SMEM>>>(hidden, memory, W_beta,
                                                  b_beta, keybuf, out);
}

// round 14
// speedup vs baseline: 1.1609x; 1.1609x over previous
#include <cuda_runtime.h>
#include <cuda_bf16.h>
#include <mma.h>
#include <math.h>
#include <stdint.h>

using namespace nvcuda;

// Problem constants (fixed shapes)
#define B_DIM 8192
#define D_DIM 512
#define H_DIM 4
#define M_DIM 128
#define W_DIM 64
#define N_DIM (H_DIM * W_DIM)   // 256
#define EPS 1e-6f

// Scratch
__device__ float g_key[(size_t)B_DIM * N_DIM];                    // 8 MB
__device__ __nv_bfloat16 g_ah[(size_t)B_DIM * D_DIM];             // hidden hi
__device__ __nv_bfloat16 g_al[(size_t)B_DIM * D_DIM];             // hidden lo
__device__ __nv_bfloat16 g_wh[(size_t)D_DIM * N_DIM];             // W_key hi
__device__ __nv_bfloat16 g_wl[(size_t)D_DIM * N_DIM];             // W_key lo

// ---------------------------------------------------------------------------
// Kernel 0: split fp32 -> bf16 (hi, lo) for hidden and W_key. (round-8 proven)
// ---------------------------------------------------------------------------
#define HID4 ((B_DIM * D_DIM) / 4)
#define WK4  ((D_DIM * N_DIM) / 4)

__device__ __forceinline__ void split_store(float4 v,
                                            __nv_bfloat16* hi,
                                            __nv_bfloat16* lo,
                                            size_t e)
{
    float x[4] = {v.x, v.y, v.z, v.w};
    __align__(8) __nv_bfloat16 h[4], l[4];
    #pragma unroll
    for (int j = 0; j < 4; j++) {
        h[j] = __float2bfloat16(x[j]);
        l[j] = __float2bfloat16(x[j] - __bfloat162float(h[j]));
    }
    *(uint2*)(hi + e) = *(uint2*)h;
    *(uint2*)(lo + e) = *(uint2*)l;
}

__global__ __launch_bounds__(256)
void split_kernel(const float* __restrict__ hidden,
                  const float* __restrict__ Wk)
{
    int i = blockIdx.x * 256 + threadIdx.x;
    if (i < HID4) {
        float4 v = ((const float4*)hidden)[i];
        split_store(v, g_ah, g_al, (size_t)i * 4);
    } else {
        int j = i - HID4;
        if (j < WK4) {
            float4 v = ((const float4*)Wk)[j];
            split_store(v, g_wh, g_wl, (size_t)j * 4);
        }
    }
}

// ---------------------------------------------------------------------------
// Kernel A: bf16 split-GEMM, 64x128 block tile, cp.async DOUBLE-BUFFERED.
// key = tanh( Ah@Wh + Ah@Wl + Al@Wh + b )
// 8 warps (2 row-groups x 4 col-groups), warp tile 32x32, K-chunk 32.
// Grid = (2, 128) = 256 blocks -> 2 CTAs/SM, 16 warps/SM.
// ---------------------------------------------------------------------------
#define GBM 64
#define GBN 128
#define KB 32
#define APITCH 40     // bf16 elems per A smem row (80 B)
#define BPITCH 136    // bf16 elems per B smem row (272 B)

// per-buffer smem bytes: Ah 64*40*2=5120, Al 5120, Bh 32*136*2=8704, Bl 8704
#define O_AH 0
#define O_AL 5120
#define O_BH 10240
#define O_BL 18944
#define BUF_BYTES 27648
#define GEMM_SMEM (2 * BUF_BYTES)      // 55296
#define EPI_PITCH 24

__device__ __forceinline__ void cpa16(void* dst, const void* src)
{
    unsigned int d = (unsigned int)__cvta_generic_to_shared(dst);
    asm volatile("cp.async.cg.shared.global [%0], [%1], 16;\n"
                 :: "r"(d), "l"(src));
}

__global__ __launch_bounds__(256)
void key_gemm_kernel(const float* __restrict__ bk,     // [256]
                     float* __restrict__ out)          // g_key [B, 256]
{
    extern __shared__ __align__(16) unsigned char dyn_smem[];

    const int tid  = threadIdx.x;
    const int warp = tid >> 5;
    const int lane = tid & 31;
    const int wr   = warp >> 2;          // 0..1 (32 rows each)
    const int wc   = warp & 3;           // 0..3 (32 cols each)

    const int row0 = blockIdx.y * GBM;
    const int col0 = blockIdx.x * GBN;

    // A tile (64x32 bf16 = 256 x 16B): 1 chunk per thread per tile
    const int aR = tid >> 2, aC = (tid & 3) * 8;
    // B tile (32x128 bf16 = 512 x 16B): 2 chunks per thread per tile
    const int bR0 = tid >> 4,          bC0 = (tid & 15) * 8;
    const int bR1 = (tid + 256) >> 4,  bC1 = (tid & 15) * 8;

    // issue one K-chunk into buffer `buf`
    auto issue_chunk = [&](int buf, int k0) {
        __nv_bfloat16* Ah = (__nv_bfloat16*)(dyn_smem + buf * BUF_BYTES + O_AH);
        __nv_bfloat16* Al = (__nv_bfloat16*)(dyn_smem + buf * BUF_BYTES + O_AL);
        __nv_bfloat16* Bh = (__nv_bfloat16*)(dyn_smem + buf * BUF_BYTES + O_BH);
        __nv_bfloat16* Bl = (__nv_bfloat16*)(dyn_smem + buf * BUF_BYTES + O_BL);
        cpa16(&Ah[aR * APITCH + aC], &g_ah[(size_t)(row0 + aR) * D_DIM + k0 + aC]);
        cpa16(&Al[aR * APITCH + aC], &g_al[(size_t)(row0 + aR) * D_DIM + k0 + aC]);
        cpa16(&Bh[bR0 * BPITCH + bC0], &g_wh[(size_t)(k0 + bR0) * N_DIM + col0 + bC0]);
        cpa16(&Bh[bR1 * BPITCH + bC1], &g_wh[(size_t)(k0 + bR1) * N_DIM + col0 + bC1]);
        cpa16(&Bl[bR0 * BPITCH + bC0], &g_wl[(size_t)(k0 + bR0) * N_DIM + col0 + bC0]);
        cpa16(&Bl[bR1 * BPITCH + bC1], &g_wl[(size_t)(k0 + bR1) * N_DIM + col0 + bC1]);
        asm volatile("cp.async.commit_group;\n");
    };

    wmma::fragment<wmma::accumulator, 16, 16, 16, float> acc[2][2];
    #pragma unroll
    for (int i = 0; i < 2; i++)
        #pragma unroll
        for (int j = 0; j < 2; j++)
            wmma::fill_fragment(acc[i][j], 0.0f);

    const int NSTEP = D_DIM / KB;   // 16

    issue_chunk(0, 0);

    #pragma unroll 1
    for (int s = 0; s < NSTEP; s++) {
        const int cbuf = s & 1;

        if (s + 1 < NSTEP) {
            issue_chunk(cbuf ^ 1, (s + 1) * KB);
            asm volatile("cp.async.wait_group 1;\n");
        } else {
            asm volatile("cp.async.wait_group 0;\n");
        }
        __syncthreads();   // chunk s resident in cbuf for all warps

        const __nv_bfloat16* Ah = (const __nv_bfloat16*)(dyn_smem + cbuf * BUF_BYTES + O_AH);
        const __nv_bfloat16* Al = (const __nv_bfloat16*)(dyn_smem + cbuf * BUF_BYTES + O_AL);
        const __nv_bfloat16* Bh = (const __nv_bfloat16*)(dyn_smem + cbuf * BUF_BYTES + O_BH);
        const __nv_bfloat16* Bl = (const __nv_bfloat16*)(dyn_smem + cbuf * BUF_BYTES + O_BL);

        #pragma unroll
        for (int kk = 0; kk < KB; kk += 16) {
            wmma::fragment<wmma::matrix_a, 16, 16, 16, __nv_bfloat16, wmma::row_major> fah[2], fal[2];
            wmma::fragment<wmma::matrix_b, 16, 16, 16, __nv_bfloat16, wmma::row_major> fbh[2], fbl[2];
            #pragma unroll
            for (int i = 0; i < 2; i++) {
                wmma::load_matrix_sync(fah[i], &Ah[(wr * 32 + i * 16) * APITCH + kk], APITCH);
                wmma::load_matrix_sync(fal[i], &Al[(wr * 32 + i * 16) * APITCH + kk], APITCH);
            }
            #pragma unroll
            for (int j = 0; j < 2; j++) {
                wmma::load_matrix_sync(fbh[j], &Bh[kk * BPITCH + wc * 32 + j * 16], BPITCH);
                wmma::load_matrix_sync(fbl[j], &Bl[kk * BPITCH + wc * 32 + j * 16], BPITCH);
            }
            #pragma unroll
            for (int i = 0; i < 2; i++)
                #pragma unroll
                for (int j = 0; j < 2; j++) {
                    wmma::mma_sync(acc[i][j], fah[i], fbh[j], acc[i][j]);
                    wmma::mma_sync(acc[i][j], fah[i], fbl[j], acc[i][j]);
                    wmma::mma_sync(acc[i][j], fal[i], fbh[j], acc[i][j]);
                }
        }
        __syncthreads();   // cbuf free before iteration s+1 overwrites it
    }

    // ---- epilogue: per-warp smem staging -> tanh(+bias) -> coalesced store
    float* scr = (float*)(dyn_smem) + warp * 16 * EPI_PITCH;   // 1536 B/warp
    const int er = lane >> 1;            // row within 16x16 tile
    const int ec = (lane & 1) * 8;       // col half (8 floats via 2 float4)

    #pragma unroll
    for (int i = 0; i < 2; i++) {
        #pragma unroll
        for (int j = 0; j < 2; j++) {
            wmma::store_matrix_sync(scr, acc[i][j], EPI_PITCH, wmma::mem_row_major);
            __syncwarp();
            const int gr = row0 + wr * 32 + i * 16 + er;
            const int gc = col0 + wc * 32 + j * 16 + ec;
            float4 c0 = *(float4*)&scr[er * EPI_PITCH + ec];
            float4 c1 = *(float4*)&scr[er * EPI_PITCH + ec + 4];
            float4 b0 = __ldg((const float4*)&bk[gc]);
            float4 b1 = __ldg((const float4*)&bk[gc + 4]);
            float4 o0, o1;
            o0.x = tanhf(c0.x + b0.x); o0.y = tanhf(c0.y + b0.y);
            o0.z = tanhf(c0.z + b0.z); o0.w = tanhf(c0.w + b0.w);
            o1.x = tanhf(c1.x + b1.x); o1.y = tanhf(c1.y + b1.y);
            o1.z = tanhf(c1.z + b1.z); o1.w = tanhf(c1.w + b1.w);
            *(float4*)&out[(size_t)gr * N_DIM + gc]     = o0;
            *(float4*)&out[(size_t)gr * N_DIM + gc + 4] = o1;
            __syncwarp();
        }
    }
}

// ---------------------------------------------------------------------------
// Kernel B: one-shot attention (round-9 proven). 256 threads per batch row.
// Tile via ONE cp.async.bulk into linear smem + mbarrier; read-side XOR
// permutation keeps LDS.128 conflict-free.
// ---------------------------------------------------------------------------
#define ATT_THREADS 256
#define ATT_SMEM (M_DIM * W_DIM * 4)   // 32768 bytes, linear [128][16] float4

__global__ __launch_bounds__(ATT_THREADS, 6)
void attn_kernel(const float* __restrict__ hidden,   // [B, 512]
                 const float* __restrict__ memory,   // [B, 128, 64]
                 const float* __restrict__ Wb,       // [512, 4]
                 const float* __restrict__ bb,       // [4]
                 const float* __restrict__ key,      // g_key [B, 256]
                 float* __restrict__ out)            // [B, 4, 128]
{
    extern __shared__ float4 tile[];                 // [128][16] linear

    __shared__ float4 key4[N_DIM / 4];
    __shared__ float  u2_s[H_DIM];
    __shared__ float  beta_s[H_DIM];
    __shared__ float4 bpart[4];
    __shared__ float4 red_s[8];
    __shared__ __align__(8) unsigned long long mbar;

    const int b    = blockIdx.x;
    const int tid  = threadIdx.x;
    const int lane = tid & 31;
    const int warp = tid >> 5;
    const int m    = tid >> 1;
    const int half = tid & 1;

    const unsigned int mbar_a =
        (unsigned int)__cvta_generic_to_shared(&mbar);

    if (tid == 0) {
        asm volatile("mbarrier.init.shared.b64 [%0], 1;" :: "r"(mbar_a) : "memory");
        asm volatile("fence.proxy.async.shared::cta;" ::: "memory");
    }
    __syncthreads();
    if (tid == 0) {
        const void* gp = (const void*)&memory[(size_t)b * M_DIM * W_DIM];
        unsigned int dst = (unsigned int)__cvta_generic_to_shared(tile);
        asm volatile("mbarrier.arrive.expect_tx.shared.b64 _, [%0], %1;"
                     :: "r"(mbar_a), "r"(ATT_SMEM) : "memory");
        asm volatile("cp.async.bulk.shared::cta.global.mbarrier::complete_tx::bytes "
                     "[%0], [%1], %2, [%3];"
                     :: "r"(dst), "l"(gp), "r"(ATT_SMEM), "r"(mbar_a) : "memory");
    }

    const float4* keyrow4 = (const float4*)&key[(size_t)b * N_DIM];

    if (warp < 4) {
        const float4* h4 = (const float4*)&hidden[(size_t)b * D_DIM];
        float4 hv = h4[warp * 32 + lane];
        const float4* wb4 = (const float4*)Wb;
        int d0 = warp * 128 + lane * 4;
        float4 w0 = wb4[d0 + 0], w1 = wb4[d0 + 1], w2 = wb4[d0 + 2], w3 = wb4[d0 + 3];
        float4 p;
        p.x = hv.x * w0.x + hv.y * w1.x + hv.z * w2.x + hv.w * w3.x;
        p.y = hv.x * w0.y + hv.y * w1.y + hv.z * w2.y + hv.w * w3.y;
        p.z = hv.x * w0.z + hv.y * w1.z + hv.z * w2.z + hv.w * w3.z;
        p.w = hv.x * w0.w + hv.y * w1.w + hv.z * w2.w + hv.w * w3.w;
        #pragma unroll
        for (int off = 16; off > 0; off >>= 1) {
            p.x += __shfl_xor_sync(0xffffffffu, p.x, off);
            p.y += __shfl_xor_sync(0xffffffffu, p.y, off);
            p.z += __shfl_xor_sync(0xffffffffu, p.z, off);
            p.w += __shfl_xor_sync(0xffffffffu, p.w, off);
        }
        if (lane == 0) bpart[warp] = p;
    } else if (warp < 6) {
        int idx = (warp - 4) * 32 + lane;
        key4[idx] = keyrow4[idx];
    } else {
        int idx = (warp - 6) * 32 + lane;
        float4 v = keyrow4[idx];
        float ss = v.x * v.x + v.y * v.y + v.z * v.z + v.w * v.w;
        #pragma unroll
        for (int off = 8; off > 0; off >>= 1)
            ss += __shfl_xor_sync(0xffffffffu, ss, off);
        if ((lane & 15) == 0)
            u2_s[(warp - 6) * 2 + (lane >> 4)] = ss + EPS;
    }

    {
        asm volatile(
            "{\n\t"
            ".reg .pred P;\n"
            "WAIT_%=:\n\t"
            "mbarrier.try_wait.parity.acquire.cta.shared::cta.b64 P, [%0], 0;\n\t"
            "@P bra DONE_%=;\n\t"
            "bra WAIT_%=;\n"
            "DONE_%=:\n\t"
            "}"
            :: "r"(mbar_a) : "memory");
    }
    __syncthreads();

    if (tid < H_DIM) {
        float s = ((const float*)&bpart[0])[tid] + ((const float*)&bpart[1])[tid]
                + ((const float*)&bpart[2])[tid] + ((const float*)&bpart[3])[tid]
                + bb[tid];
        beta_s[tid] = (s > 15.f) ? s : __logf(1.f + __expf(s));
    }

    const int perm = ((m & 3) << 1) | half;
    float v2 = 0.f;
    float num[H_DIM] = {0.f, 0.f, 0.f, 0.f};
    #pragma unroll
    for (int i = 0; i < 8; i++) {
        int ws = (half * 8 + i) ^ perm;
        float4 v = tile[m * 16 + ws];
        v2 += v.x * v.x + v.y * v.y + v.z * v.z + v.w * v.w;
        #pragma unroll
        for (int h = 0; h < H_DIM; h++) {
            float4 kh = key4[h * 16 + ws];
            num[h] += kh.x * v.x + kh.y * v.y + kh.z * v.z + kh.w * v.w;
        }
    }
    #pragma unroll
    for (int h = 0; h < H_DIM; h++)
        num[h] += __shfl_xor_sync(0xffffffffu, num[h], 1);
    v2 += __shfl_xor_sync(0xffffffffu, v2, 1);
    v2 += EPS;

    __syncthreads();

    float e[H_DIM];
    #pragma unroll
    for (int h = 0; h < H_DIM; h++) {
        float den = sqrtf(u2_s[h] * v2);
        float kk  = num[h] / (den + EPS);
        e[h] = __expf(kk * beta_s[h]);
    }

    {
        float4 es = make_float4(e[0], e[1], e[2], e[3]);
        #pragma unroll
        for (int off = 16; off > 0; off >>= 1) {
            es.x += __shfl_xor_sync(0xffffffffu, es.x, off);
            es.y += __shfl_xor_sync(0xffffffffu, es.y, off);
            es.z += __shfl_xor_sync(0xffffffffu, es.z, off);
            es.w += __shfl_xor_sync(0xffffffffu, es.w, off);
        }
        if (lane == 0) red_s[warp] = es;
    }
    __syncthreads();

    float4 t0 = red_s[0], t1 = red_s[1], t2 = red_s[2], t3 = red_s[3];
    float4 t4 = red_s[4], t5 = red_s[5], t6 = red_s[6], t7 = red_s[7];
    float sm[H_DIM];
    sm[0] = 0.5f * (t0.x + t1.x + t2.x + t3.x + t4.x + t5.x + t6.x + t7.x);
    sm[1] = 0.5f * (t0.y + t1.y + t2.y + t3.y + t4.y + t5.y + t6.y + t7.y);
    sm[2] = 0.5f * (t0.z + t1.z + t2.z + t3.z + t4.z + t5.z + t6.z + t7.z);
    sm[3] = 0.5f * (t0.w + t1.w + t2.w + t3.w + t4.w + t5.w + t6.w + t7.w);

    #pragma unroll
    for (int j = 0; j < 2; j++) {
        int h = half * 2 + j;
        out[((size_t)b * H_DIM + h) * M_DIM + m] = e[h] / sm[h];
    }
}

// ---------------------------------------------------------------------------
// Launch
// ---------------------------------------------------------------------------
extern "C" void kernel_launch(void* const* d_in, const int* in_sizes, int n_in,
                              void* d_out, int out_size)
{
    const float* hidden = (const float*)d_in[0];   // [8192, 512]
    const float* memory = (const float*)d_in[1];   // [8192, 128, 64]
    const float* W_key  = (const float*)d_in[2];   // [512, 256]
    const float* b_key  = (const float*)d_in[3];   // [256]
    const float* W_beta = (const float*)d_in[4];   // [512, 4]
    const float* b_beta = (const float*)d_in[5];   // [4]
    float* out = (float*)d_out;                    // [8192, 4, 128]

    float* keybuf;
    cudaGetSymbolAddress((void**)&keybuf, g_key);

    cudaFuncSetAttribute(key_gemm_kernel,
                         cudaFuncAttributeMaxDynamicSharedMemorySize,
                         GEMM_SMEM);

    int splitBlocks = (HID4 + WK4 + 255) / 256;
    split_kernel<<<splitBlocks, 256>>>(hidden, W_key);

    dim3 gridA(N_DIM / GBN, B_DIM / GBM);   // (2, 128) = 256 blocks
    key_gemm_kernel<<<gridA, 256, GEMM_SMEM>>>(b_key, keybuf);

    attn_kernel<<<B_DIM, ATT_THREADS, ATT_SMEM>>>(hidden, memory, W_beta,
                                                  b_beta, keybuf, out);
}

// round 15
// speedup vs baseline: 1.4372x; 1.2379x over previous
#include <cuda_runtime.h>
#include <cuda_bf16.h>
#include <mma.h>
#include <math.h>
#include <stdint.h>

using namespace nvcuda;

// Problem constants (fixed shapes)
#define B_DIM 8192
#define D_DIM 512
#define H_DIM 4
#define M_DIM 128
#define W_DIM 64
#define N_DIM (H_DIM * W_DIM)   // 256
#define EPS 1e-6f

// Scratch
__device__ float g_key[(size_t)B_DIM * N_DIM];                    // 8 MB
__device__ __nv_bfloat16 g_ah[(size_t)B_DIM * D_DIM];             // hidden hi
__device__ __nv_bfloat16 g_al[(size_t)B_DIM * D_DIM];             // hidden lo
__device__ __nv_bfloat16 g_wh[(size_t)D_DIM * N_DIM];             // W_key hi
__device__ __nv_bfloat16 g_wl[(size_t)D_DIM * N_DIM];             // W_key lo

// ---------------------------------------------------------------------------
// Kernel 0: split fp32 -> bf16 (hi, lo) for hidden and W_key. (round-8 proven)
// ---------------------------------------------------------------------------
#define HID4 ((B_DIM * D_DIM) / 4)
#define WK4  ((D_DIM * N_DIM) / 4)

__device__ __forceinline__ void split_store(float4 v,
                                            __nv_bfloat16* hi,
                                            __nv_bfloat16* lo,
                                            size_t e)
{
    float x[4] = {v.x, v.y, v.z, v.w};
    __align__(8) __nv_bfloat16 h[4], l[4];
    #pragma unroll
    for (int j = 0; j < 4; j++) {
        h[j] = __float2bfloat16(x[j]);
        l[j] = __float2bfloat16(x[j] - __bfloat162float(h[j]));
    }
    *(uint2*)(hi + e) = *(uint2*)h;
    *(uint2*)(lo + e) = *(uint2*)l;
}

__global__ __launch_bounds__(256)
void split_kernel(const float* __restrict__ hidden,
                  const float* __restrict__ Wk)
{
    int i = blockIdx.x * 256 + threadIdx.x;
    if (i < HID4) {
        float4 v = ((const float4*)hidden)[i];
        split_store(v, g_ah, g_al, (size_t)i * 4);
    } else {
        int j = i - HID4;
        if (j < WK4) {
            float4 v = ((const float4*)Wk)[j];
            split_store(v, g_wh, g_wl, (size_t)j * 4);
        }
    }
}

// ---------------------------------------------------------------------------
// Kernel A: bf16 split-GEMM, 64x128 block tile, cp.async double-buffered.
// (round-14 proven, unchanged)
// ---------------------------------------------------------------------------
#define GBM 64
#define GBN 128
#define KB 32
#define APITCH 40
#define BPITCH 136
#define O_AH 0
#define O_AL 5120
#define O_BH 10240
#define O_BL 18944
#define BUF_BYTES 27648
#define GEMM_SMEM (2 * BUF_BYTES)
#define EPI_PITCH 24

__device__ __forceinline__ void cpa16(void* dst, const void* src)
{
    unsigned int d = (unsigned int)__cvta_generic_to_shared(dst);
    asm volatile("cp.async.cg.shared.global [%0], [%1], 16;\n"
                 :: "r"(d), "l"(src));
}

__global__ __launch_bounds__(256)
void key_gemm_kernel(const float* __restrict__ bk,     // [256]
                     float* __restrict__ out)          // g_key [B, 256]
{
    extern __shared__ __align__(16) unsigned char dyn_smem[];

    const int tid  = threadIdx.x;
    const int warp = tid >> 5;
    const int lane = tid & 31;
    const int wr   = warp >> 2;
    const int wc   = warp & 3;

    const int row0 = blockIdx.y * GBM;
    const int col0 = blockIdx.x * GBN;

    const int aR = tid >> 2, aC = (tid & 3) * 8;
    const int bR0 = tid >> 4,          bC0 = (tid & 15) * 8;
    const int bR1 = (tid + 256) >> 4,  bC1 = (tid & 15) * 8;

    auto issue_chunk = [&](int buf, int k0) {
        __nv_bfloat16* Ah = (__nv_bfloat16*)(dyn_smem + buf * BUF_BYTES + O_AH);
        __nv_bfloat16* Al = (__nv_bfloat16*)(dyn_smem + buf * BUF_BYTES + O_AL);
        __nv_bfloat16* Bh = (__nv_bfloat16*)(dyn_smem + buf * BUF_BYTES + O_BH);
        __nv_bfloat16* Bl = (__nv_bfloat16*)(dyn_smem + buf * BUF_BYTES + O_BL);
        cpa16(&Ah[aR * APITCH + aC], &g_ah[(size_t)(row0 + aR) * D_DIM + k0 + aC]);
        cpa16(&Al[aR * APITCH + aC], &g_al[(size_t)(row0 + aR) * D_DIM + k0 + aC]);
        cpa16(&Bh[bR0 * BPITCH + bC0], &g_wh[(size_t)(k0 + bR0) * N_DIM + col0 + bC0]);
        cpa16(&Bh[bR1 * BPITCH + bC1], &g_wh[(size_t)(k0 + bR1) * N_DIM + col0 + bC1]);
        cpa16(&Bl[bR0 * BPITCH + bC0], &g_wl[(size_t)(k0 + bR0) * N_DIM + col0 + bC0]);
        cpa16(&Bl[bR1 * BPITCH + bC1], &g_wl[(size_t)(k0 + bR1) * N_DIM + col0 + bC1]);
        asm volatile("cp.async.commit_group;\n");
    };

    wmma::fragment<wmma::accumulator, 16, 16, 16, float> acc[2][2];
    #pragma unroll
    for (int i = 0; i < 2; i++)
        #pragma unroll
        for (int j = 0; j < 2; j++)
            wmma::fill_fragment(acc[i][j], 0.0f);

    const int NSTEP = D_DIM / KB;   // 16

    issue_chunk(0, 0);

    #pragma unroll 1
    for (int s = 0; s < NSTEP; s++) {
        const int cbuf = s & 1;

        if (s + 1 < NSTEP) {
            issue_chunk(cbuf ^ 1, (s + 1) * KB);
            asm volatile("cp.async.wait_group 1;\n");
        } else {
            asm volatile("cp.async.wait_group 0;\n");
        }
        __syncthreads();

        const __nv_bfloat16* Ah = (const __nv_bfloat16*)(dyn_smem + cbuf * BUF_BYTES + O_AH);
        const __nv_bfloat16* Al = (const __nv_bfloat16*)(dyn_smem + cbuf * BUF_BYTES + O_AL);
        const __nv_bfloat16* Bh = (const __nv_bfloat16*)(dyn_smem + cbuf * BUF_BYTES + O_BH);
        const __nv_bfloat16* Bl = (const __nv_bfloat16*)(dyn_smem + cbuf * BUF_BYTES + O_BL);

        #pragma unroll
        for (int kk = 0; kk < KB; kk += 16) {
            wmma::fragment<wmma::matrix_a, 16, 16, 16, __nv_bfloat16, wmma::row_major> fah[2], fal[2];
            wmma::fragment<wmma::matrix_b, 16, 16, 16, __nv_bfloat16, wmma::row_major> fbh[2], fbl[2];
            #pragma unroll
            for (int i = 0; i < 2; i++) {
                wmma::load_matrix_sync(fah[i], &Ah[(wr * 32 + i * 16) * APITCH + kk], APITCH);
                wmma::load_matrix_sync(fal[i], &Al[(wr * 32 + i * 16) * APITCH + kk], APITCH);
            }
            #pragma unroll
            for (int j = 0; j < 2; j++) {
                wmma::load_matrix_sync(fbh[j], &Bh[kk * BPITCH + wc * 32 + j * 16], BPITCH);
                wmma::load_matrix_sync(fbl[j], &Bl[kk * BPITCH + wc * 32 + j * 16], BPITCH);
            }
            #pragma unroll
            for (int i = 0; i < 2; i++)
                #pragma unroll
                for (int j = 0; j < 2; j++) {
                    wmma::mma_sync(acc[i][j], fah[i], fbh[j], acc[i][j]);
                    wmma::mma_sync(acc[i][j], fah[i], fbl[j], acc[i][j]);
                    wmma::mma_sync(acc[i][j], fal[i], fbh[j], acc[i][j]);
                }
        }
        __syncthreads();
    }

    float* scr = (float*)(dyn_smem) + warp * 16 * EPI_PITCH;
    const int er = lane >> 1;
    const int ec = (lane & 1) * 8;

    #pragma unroll
    for (int i = 0; i < 2; i++) {
        #pragma unroll
        for (int j = 0; j < 2; j++) {
            wmma::store_matrix_sync(scr, acc[i][j], EPI_PITCH, wmma::mem_row_major);
            __syncwarp();
            const int gr = row0 + wr * 32 + i * 16 + er;
            const int gc = col0 + wc * 32 + j * 16 + ec;
            float4 c0 = *(float4*)&scr[er * EPI_PITCH + ec];
            float4 c1 = *(float4*)&scr[er * EPI_PITCH + ec + 4];
            float4 b0 = __ldg((const float4*)&bk[gc]);
            float4 b1 = __ldg((const float4*)&bk[gc + 4]);
            float4 o0, o1;
            o0.x = tanhf(c0.x + b0.x); o0.y = tanhf(c0.y + b0.y);
            o0.z = tanhf(c0.z + b0.z); o0.w = tanhf(c0.w + b0.w);
            o1.x = tanhf(c1.x + b1.x); o1.y = tanhf(c1.y + b1.y);
            o1.z = tanhf(c1.z + b1.z); o1.w = tanhf(c1.w + b1.w);
            *(float4*)&out[(size_t)gr * N_DIM + gc]     = o0;
            *(float4*)&out[(size_t)gr * N_DIM + gc + 4] = o1;
            __syncwarp();
        }
    }
}

// ---------------------------------------------------------------------------
// Kernel B: one-shot attention, 256 threads. NEW 2-rows x 4-slots blocking:
// thread (g = tid>>2, q = tid&3) handles rows {2g, 2g+1}, slots
// (q + 4j) ^ ((g&1)<<2), j = 0..3.  LDS/thread: 8 tile + 16 key = 24 (was 40).
// Key loads amortize over 2 rows. Slot map is bijective per row and
// conflict-free per LDS quarter-warp phase (classes {q+4j} and ^4 tile all
// 8 bank-quads). Transpose-reduce delivers head q's sums to lane q.
// ---------------------------------------------------------------------------
#define ATT_THREADS 256
#define ATT_SMEM (M_DIM * W_DIM * 4)   // 32768 bytes, linear [128][16] float4

__global__ __launch_bounds__(ATT_THREADS, 6)
void attn_kernel(const float* __restrict__ hidden,   // [B, 512]
                 const float* __restrict__ memory,   // [B, 128, 64]
                 const float* __restrict__ Wb,       // [512, 4]
                 const float* __restrict__ bb,       // [4]
                 const float* __restrict__ key,      // g_key [B, 256]
                 float* __restrict__ out)            // [B, 4, 128]
{
    extern __shared__ float4 tile[];                 // [128][16] linear

    __shared__ float4 key4[N_DIM / 4];
    __shared__ float  u2_s[H_DIM];
    __shared__ float  beta_s[H_DIM];
    __shared__ float4 bpart[4];
    __shared__ float  red_h[H_DIM][8];               // [head][warp]
    __shared__ __align__(8) unsigned long long mbar;

    const int b    = blockIdx.x;
    const int tid  = threadIdx.x;
    const int lane = tid & 31;
    const int warp = tid >> 5;
    const int g    = tid >> 2;          // row-pair group 0..63
    const int q    = tid & 3;           // quarter within group
    const int r0   = 2 * g;             // first row of pair
    const int pxor = (g & 1) << 2;

    const unsigned int mbar_a =
        (unsigned int)__cvta_generic_to_shared(&mbar);

    if (tid == 0) {
        asm volatile("mbarrier.init.shared.b64 [%0], 1;" :: "r"(mbar_a) : "memory");
        asm volatile("fence.proxy.async.shared::cta;" ::: "memory");
    }
    __syncthreads();
    if (tid == 0) {
        const void* gp = (const void*)&memory[(size_t)b * M_DIM * W_DIM];
        unsigned int dst = (unsigned int)__cvta_generic_to_shared(tile);
        asm volatile("mbarrier.arrive.expect_tx.shared.b64 _, [%0], %1;"
                     :: "r"(mbar_a), "r"(ATT_SMEM) : "memory");
        asm volatile("cp.async.bulk.shared::cta.global.mbarrier::complete_tx::bytes "
                     "[%0], [%1], %2, [%3];"
                     :: "r"(dst), "l"(gp), "r"(ATT_SMEM), "r"(mbar_a) : "memory");
    }

    // ---- overlap with the DMA: beta partials (warps 0-3), key (4-5), u2 (6-7)
    const float4* keyrow4 = (const float4*)&key[(size_t)b * N_DIM];

    if (warp < 4) {
        const float4* h4 = (const float4*)&hidden[(size_t)b * D_DIM];
        float4 hv = h4[warp * 32 + lane];
        const float4* wb4 = (const float4*)Wb;
        int d0 = warp * 128 + lane * 4;
        float4 w0 = wb4[d0 + 0], w1 = wb4[d0 + 1], w2 = wb4[d0 + 2], w3 = wb4[d0 + 3];
        float4 p;
        p.x = hv.x * w0.x + hv.y * w1.x + hv.z * w2.x + hv.w * w3.x;
        p.y = hv.x * w0.y + hv.y * w1.y + hv.z * w2.y + hv.w * w3.y;
        p.z = hv.x * w0.z + hv.y * w1.z + hv.z * w2.z + hv.w * w3.z;
        p.w = hv.x * w0.w + hv.y * w1.w + hv.z * w2.w + hv.w * w3.w;
        #pragma unroll
        for (int off = 16; off > 0; off >>= 1) {
            p.x += __shfl_xor_sync(0xffffffffu, p.x, off);
            p.y += __shfl_xor_sync(0xffffffffu, p.y, off);
            p.z += __shfl_xor_sync(0xffffffffu, p.z, off);
            p.w += __shfl_xor_sync(0xffffffffu, p.w, off);
        }
        if (lane == 0) bpart[warp] = p;
    } else if (warp < 6) {
        int idx = (warp - 4) * 32 + lane;
        key4[idx] = keyrow4[idx];
    } else {
        int idx = (warp - 6) * 32 + lane;
        float4 v = keyrow4[idx];
        float ss = v.x * v.x + v.y * v.y + v.z * v.z + v.w * v.w;
        #pragma unroll
        for (int off = 8; off > 0; off >>= 1)
            ss += __shfl_xor_sync(0xffffffffu, ss, off);
        if ((lane & 15) == 0)
            u2_s[(warp - 6) * 2 + (lane >> 4)] = ss + EPS;
    }

    {
        asm volatile(
            "{\n\t"
            ".reg .pred P;\n"
            "WAIT_%=:\n\t"
            "mbarrier.try_wait.parity.acquire.cta.shared::cta.b64 P, [%0], 0;\n\t"
            "@P bra DONE_%=;\n\t"
            "bra WAIT_%=;\n"
            "DONE_%=:\n\t"
            "}"
            :: "r"(mbar_a) : "memory");
    }
    __syncthreads();   // barrier 1: tile, key4, u2_s, bpart visible

    if (tid < H_DIM) {
        float s = ((const float*)&bpart[0])[tid] + ((const float*)&bpart[1])[tid]
                + ((const float*)&bpart[2])[tid] + ((const float*)&bpart[3])[tid]
                + bb[tid];
        beta_s[tid] = (s > 15.f) ? s : __logf(1.f + __expf(s));
    }

    // ---- dot loop: 2 rows x 4 slots, key loads shared across the row pair
    float v2a = 0.f, v2b = 0.f;
    float num0[4] = {0.f, 0.f, 0.f, 0.f};   // row r0, heads 0..3
    float num1[4] = {0.f, 0.f, 0.f, 0.f};   // row r0+1
    #pragma unroll
    for (int j = 0; j < 4; j++) {
        const int slot = (q + 4 * j) ^ pxor;
        float4 k0 = key4[slot];
        float4 k1 = key4[16 + slot];
        float4 k2 = key4[32 + slot];
        float4 k3 = key4[48 + slot];
        float4 va = tile[r0 * 16 + slot];
        float4 vb = tile[r0 * 16 + 16 + slot];
        v2a += va.x * va.x + va.y * va.y + va.z * va.z + va.w * va.w;
        v2b += vb.x * vb.x + vb.y * vb.y + vb.z * vb.z + vb.w * vb.w;
        num0[0] += k0.x * va.x + k0.y * va.y + k0.z * va.z + k0.w * va.w;
        num0[1] += k1.x * va.x + k1.y * va.y + k1.z * va.z + k1.w * va.w;
        num0[2] += k2.x * va.x + k2.y * va.y + k2.z * va.z + k2.w * va.w;
        num0[3] += k3.x * va.x + k3.y * va.y + k3.z * va.z + k3.w * va.w;
        num1[0] += k0.x * vb.x + k0.y * vb.y + k0.z * vb.z + k0.w * vb.w;
        num1[1] += k1.x * vb.x + k1.y * vb.y + k1.z * vb.z + k1.w * vb.w;
        num1[2] += k2.x * vb.x + k2.y * vb.y + k2.z * vb.z + k2.w * vb.w;
        num1[3] += k3.x * vb.x + k3.y * vb.y + k3.z * vb.z + k3.w * vb.w;
    }

    // ---- group reduction (4 lanes: xor 1, 2)
    // v2: full butterfly (all lanes need both rows' v2)
    v2a += __shfl_xor_sync(0xffffffffu, v2a, 1);
    v2a += __shfl_xor_sync(0xffffffffu, v2a, 2);
    v2b += __shfl_xor_sync(0xffffffffu, v2b, 1);
    v2b += __shfl_xor_sync(0xffffffffu, v2b, 2);
    v2a += EPS;
    v2b += EPS;

    // num: transpose-reduce -> lane q gets head q's totals
    const int myh  = q & 1;
    const int bit1 = (q >> 1) & 1;
    float numf0, numf1;
    {
        float keep0 = myh ? num0[1] : num0[0];
        float send0 = myh ? num0[0] : num0[1];
        float y0 = keep0 + __shfl_xor_sync(0xffffffffu, send0, 1);
        float keep1 = myh ? num0[3] : num0[2];
        float send1 = myh ? num0[2] : num0[3];
        float y1 = keep1 + __shfl_xor_sync(0xffffffffu, send1, 1);
        float keep = bit1 ? y1 : y0;
        float send = bit1 ? y0 : y1;
        numf0 = keep + __shfl_xor_sync(0xffffffffu, send, 2);
    }
    {
        float keep0 = myh ? num1[1] : num1[0];
        float send0 = myh ? num1[0] : num1[1];
        float y0 = keep0 + __shfl_xor_sync(0xffffffffu, send0, 1);
        float keep1 = myh ? num1[3] : num1[2];
        float send1 = myh ? num1[2] : num1[3];
        float y1 = keep1 + __shfl_xor_sync(0xffffffffu, send1, 1);
        float keep = bit1 ? y1 : y0;
        float send = bit1 ? y0 : y1;
        numf1 = keep + __shfl_xor_sync(0xffffffffu, send, 2);
    }

    __syncthreads();   // barrier 2: beta_s ready

    // ---- logits -> exp (head q, rows r0, r0+1)
    const float u2q   = u2_s[q];
    const float betaq = beta_s[q];
    float e0 = __expf(numf0 / (sqrtf(u2q * v2a) + EPS) * betaq);
    float e1 = __expf(numf1 / (sqrtf(u2q * v2b) + EPS) * betaq);

    // ---- per-head block sum: butterfly over same-q lanes, then cross-warp
    float s = e0 + e1;
    s += __shfl_xor_sync(0xffffffffu, s, 4);
    s += __shfl_xor_sync(0xffffffffu, s, 8);
    s += __shfl_xor_sync(0xffffffffu, s, 16);
    if (lane < 4) red_h[q][warp] = s;
    __syncthreads();   // barrier 3

    float4 sA = *(float4*)&red_h[q][0];
    float4 sB = *(float4*)&red_h[q][4];
    float sm = sA.x + sA.y + sA.z + sA.w + sB.x + sB.y + sB.z + sB.w;
    float rs = 1.0f / sm;

    *(float2*)&out[((size_t)b * H_DIM + q) * M_DIM + r0] =
        make_float2(e0 * rs, e1 * rs);
}

// ---------------------------------------------------------------------------
// Launch
// ---------------------------------------------------------------------------
extern "C" void kernel_launch(void* const* d_in, const int* in_sizes, int n_in,
                              void* d_out, int out_size)
{
    const float* hidden = (const float*)d_in[0];   // [8192, 512]
    const float* memory = (const float*)d_in[1];   // [8192, 128, 64]
    const float* W_key  = (const float*)d_in[2];   // [512, 256]
    const float* b_key  = (const float*)d_in[3];   // [256]
    const float* W_beta = (const float*)d_in[4];   // [512, 4]
    const float* b_beta = (const float*)d_in[5];   // [4]
    float* out = (float*)d_out;                    // [8192, 4, 128]

    float* keybuf;
    cudaGetSymbolAddress((void**)&keybuf, g_key);

    cudaFuncSetAttribute(key_gemm_kernel,
                         cudaFuncAttributeMaxDynamicSharedMemorySize,
                         GEMM_SMEM);

    int splitBlocks = (HID4 + WK4 + 255) / 256;
    split_kernel<<<splitBlocks, 256>>>(hidden, W_key);

    dim3 gridA(N_DIM / GBN, B_DIM / GBM);   // (2, 128) = 256 blocks
    key_gemm_kernel<<<gridA, 256, GEMM_SMEM>>>(b_key, keybuf);

    attn_kernel<<<B_DIM, ATT_THREADS, ATT_SMEM>>>(hidden, memory, W_beta,
                                                  b_beta, keybuf, out);
}